// round 16
// baseline (speedup 1.0000x reference)
#include <cuda_runtime.h>
#include <cstdint>

#define BB   256
#define IN   1024
#define OUTN 1024

#define OT 32    // out-cols per block (lane dimension)
#define BT 8     // batch rows per block (4 warps x 2 rows)
#define IC 64    // i-chunk
#define NBUF 3   // triple buffer
#define NCHUNK (IN / IC)

// __device__ scratch (no allocation)
__device__ float g_WT2[IN * OUTN];                // pair-interleaved: [i/2][o][2]

typedef unsigned long long ull;

__device__ __forceinline__ float tanh_fast(float x) {
    float y;
    asm("tanh.approx.f32 %0, %1;" : "=f"(y) : "f"(x));
    return y;
}

// ---- Blackwell packed f32x2 ops (PTX-only) ----
__device__ __forceinline__ ull pack2(float lo, float hi) {
    ull r; asm("mov.b64 %0, {%1, %2};" : "=l"(r) : "f"(lo), "f"(hi)); return r;
}
__device__ __forceinline__ ull dup2(float v) {
    ull r; asm("mov.b64 %0, {%1, %1};" : "=l"(r) : "f"(v)); return r;
}
__device__ __forceinline__ void unpack2(ull v, float& lo, float& hi) {
    asm("mov.b64 {%0, %1}, %2;" : "=f"(lo), "=f"(hi) : "l"(v));
}
__device__ __forceinline__ ull mul2(ull a, ull b) {
    ull d; asm("mul.rn.f32x2 %0, %1, %2;" : "=l"(d) : "l"(a), "l"(b)); return d;
}
__device__ __forceinline__ ull add2(ull a, ull b) {
    ull d; asm("add.rn.f32x2 %0, %1, %2;" : "=l"(d) : "l"(a), "l"(b)); return d;
}
__device__ __forceinline__ ull fma2p(ull a, ull b, ull c) {
    ull d; asm("fma.rn.f32x2 %0, %1, %2, %3;" : "=l"(d) : "l"(a), "l"(b), "l"(c)); return d;
}

// ---- cp.async 16B ----
__device__ __forceinline__ void cp16(uint32_t dst_smem, const void* src) {
    asm volatile("cp.async.cg.shared.global [%0], [%1], 16;"
                 :: "r"(dst_smem), "l"(src));
}
__device__ __forceinline__ void cp_commit() {
    asm volatile("cp.async.commit_group;" ::: "memory");
}
template <int N> __device__ __forceinline__ void cp_wait() {
    asm volatile("cp.async.wait_group %0;" :: "n"(N) : "memory");
}

// ---------------------------------------------------------------------------
// Prep kernel: W_eff -> pair-interleaved g_WT2[i/2][o][2]. grid (32, 8).
// 128o x 32i tile, 4 o-rows/thread -> 16 independent float4 LDGs (MLP 16).
// Both smem phases verified conflict-free (stride-37 rows).
// ---------------------------------------------------------------------------
__global__ __launch_bounds__(256) void prep_kernel(
    const float* __restrict__ W,
    const float* __restrict__ fl)
{
    __shared__ float tile[128][37];
    const int itile = blockIdx.x * 32;
    const int otile = blockIdx.y * 128;
    const int o0 = threadIdx.x >> 3;          // 0..31
    const int cg = (threadIdx.x & 7) * 4;     // i-group

    float4 wv[4], f0[4], f1[4], f2[4];
    #pragma unroll
    for (int r = 0; r < 4; r++) {
        int idx = (otile + o0 + 32 * r) * IN + itile + cg;
        wv[r] = *reinterpret_cast<const float4*>(&W[idx]);
        f0[r] = *reinterpret_cast<const float4*>(&fl[3 * idx + 0]);
        f1[r] = *reinterpret_cast<const float4*>(&fl[3 * idx + 4]);
        f2[r] = *reinterpret_cast<const float4*>(&fl[3 * idx + 8]);
    }

    #pragma unroll
    for (int r = 0; r < 4; r++) {
        int o = o0 + 32 * r;
        float wa[4] = {wv[r].x, wv[r].y, wv[r].z, wv[r].w};
        float la[12] = {f0[r].x, f0[r].y, f0[r].z, f0[r].w,
                        f1[r].x, f1[r].y, f1[r].z, f1[r].w,
                        f2[r].x, f2[r].y, f2[r].z, f2[r].w};
        #pragma unroll
        for (int j = 0; j < 4; j++) {
            float w  = wa[j];
            float l0 = la[3 * j + 0];
            float l1 = la[3 * j + 1];
            float l2 = la[3 * j + 2];
            float m  = fmaxf(l0, fmaxf(l1, l2));
            float e0 = __expf(l0 - m);
            float e1 = __expf(l1 - m);
            float e2 = __expf(l2 - m);
            float inv = 1.0f / (e0 + e1 + e2);
            float t = tanh_fast(w);
            float s = __sinf(w);
            tile[o][cg + j] = (e0 * w + e1 * t + e2 * s) * inv;
        }
    }
    __syncthreads();

    // write-out: tc = o (0..127), tr selects ip half; 8 ips per thread
    const int tc = threadIdx.x & 127;
    const int tr = threadIdx.x >> 7;      // 0..1
    #pragma unroll
    for (int k = 0; k < 8; k++) {
        int ip = tr + 2 * k;              // 0..15
        int gi = itile + ip * 2;
        float2 v;
        v.x = tile[tc][ip * 2];
        v.y = tile[tc][ip * 2 + 1];
        *reinterpret_cast<float2*>(
            &g_WT2[(gi >> 1) * (OUTN * 2) + (otile + tc) * 2]) = v;
    }
}

// ---------------------------------------------------------------------------
// Kernel 2: out[b,o] = sum_i tanh(h[b,i] * W_eff[o,i]) + bias[o]
// f32x2 lanes pack (i, i+1) per batch row (w via LDS.64 pair-interleaved,
// h via LDS.64 broadcast of row-major tile).
// Hybrid split 7:9 over period-16 ip pattern (LP optimum for deg-5 costs):
//   MUFU ips ({0,2,5,7,9,11,14}): tanh.approx per element
//   poly ips: deg-5 odd  z*(1 + u(C3 + C5 u)),  u = z^2
// Per 1024 lane-elems per SMSP: fma 118 cyc, MUFU 112 cyc -> balanced.
// ---------------------------------------------------------------------------
__global__ __launch_bounds__(128, 7) void qfbn_main_kernel(
    const float* __restrict__ h,
    const float* __restrict__ bias,
    float* __restrict__ out)
{
    __shared__ __align__(16) float ws2[NBUF][IC / 2][OT][2];  // [buf][ipair][o][2]
    __shared__ __align__(16) float hs[NBUF][BT][IC];          // row-major h tile

    const int tid   = threadIdx.x;
    const int lane  = tid & 31;
    const int warp  = tid >> 5;               // 0..3
    const int rA    = 2 * warp;               // this warp's batch rows
    const int rB    = 2 * warp + 1;
    const int otile = blockIdx.x * OT;
    const int btile = blockIdx.y * BT;

    // deg-5 minimax-ish odd tanh on [0, 0.7]
    const ull C3_2 = dup2(-0.33270f);
    const ull C5_2 = dup2( 0.12620f);
    const ull ONE2 = dup2( 1.0f);

    ull accMA = 0, accMB = 0;   // MUFU-path (packed over i-pairs)
    ull accPA = 0, accPB = 0;   // poly-path

    const int w_r0 = tid >> 4;           // prefetch: W pairrow for k=0
    const int w_q  = tid & 15;
    const int h_r  = tid >> 4;           // h row (0..7)
    const int h_q  = tid & 15;           // 16B quad in row

    auto prefetch = [&](int buf, int c) {
        const int ibase = c * IC;
        #pragma unroll
        for (int k = 0; k < 4; k++) {
            int r = w_r0 + k * 8;
            uint32_t dst = (uint32_t)__cvta_generic_to_shared(&ws2[buf][r][w_q * 2][0]);
            cp16(dst, &g_WT2[((ibase >> 1) + r) * (OUTN * 2) + otile * 2 + w_q * 4]);
        }
        {
            uint32_t dst = (uint32_t)__cvta_generic_to_shared(&hs[buf][h_r][h_q * 4]);
            cp16(dst, &h[(btile + h_r) * IN + ibase + h_q * 4]);
        }
        cp_commit();
    };

    prefetch(0, 0);
    prefetch(1, 1);

    int buf = 0;
    for (int c = 0; c < NCHUNK; c++) {
        if (c + 1 < NCHUNK) cp_wait<1>();
        else                cp_wait<0>();
        __syncthreads();
        if (c + 2 < NCHUNK) {
            int nbuf = buf + 2; if (nbuf >= NBUF) nbuf -= NBUF;
            prefetch(nbuf, c + 2);
        }

        #pragma unroll
        for (int ip = 0; ip < IC / 2; ip++) {
            // w pair (w_i, w_i+1): LDS.64
            ull w2 = *reinterpret_cast<const ull*>(&ws2[buf][ip][lane][0]);
            // h pairs for both rows: LDS.64 broadcast
            ull hA = *reinterpret_cast<const ull*>(&hs[buf][rA][2 * ip]);
            ull hB = *reinterpret_cast<const ull*>(&hs[buf][rB][2 * ip]);
            ull zA = mul2(hA, w2);
            ull zB = mul2(hB, w2);

            // period-16 pattern: 7 MUFU : 9 poly (compile-time selection)
            const int m = ip & 15;
            const bool is_mufu = (m == 0 || m == 2 || m == 5 || m == 7 ||
                                  m == 9 || m == 11 || m == 14);
            if (is_mufu) {
                float x0, x1, y0, y1;
                unpack2(zA, x0, x1);
                unpack2(zB, y0, y1);
                accMA = add2(accMA, pack2(tanh_fast(x0), tanh_fast(x1)));
                accMB = add2(accMB, pack2(tanh_fast(y0), tanh_fast(y1)));
            } else {
                ull uA = mul2(zA, zA);
                ull uB = mul2(zB, zB);
                ull qA = fma2p(uA, C5_2, C3_2);
                ull qB = fma2p(uB, C5_2, C3_2);
                ull rA2 = fma2p(qA, uA, ONE2);
                ull rB2 = fma2p(qB, uB, ONE2);
                accPA = fma2p(zA, rA2, accPA);
                accPB = fma2p(zB, rB2, accPB);
            }
        }

        if (++buf >= NBUF) buf = 0;
    }

    // Epilogue: fold packed i-halves
    float mAl, mAh, mBl, mBh, pAl, pAh, pBl, pBh;
    unpack2(accMA, mAl, mAh);
    unpack2(accMB, mBl, mBh);
    unpack2(accPA, pAl, pAh);
    unpack2(accPB, pBl, pBh);

    int o  = otile + lane;
    float bv = bias[o];
    out[(btile + rA) * OUTN + o] = ((mAl + mAh) + (pAl + pAh)) + bv;
    out[(btile + rB) * OUTN + o] = ((mBl + mBh) + (pBl + pBh)) + bv;
}

// ---------------------------------------------------------------------------
// Inputs (metadata order): h, W, b, f_logits. Output float (B, OUT).
// Graph-capturable: two kernel launches, no sync, no alloc.
// ---------------------------------------------------------------------------
extern "C" void kernel_launch(void* const* d_in, const int* in_sizes, int n_in,
                              void* d_out, int out_size)
{
    const float* h        = (const float*)d_in[0];
    const float* W        = (const float*)d_in[1];
    const float* bias     = (const float*)d_in[2];
    const float* f_logits = (const float*)d_in[3];
    float* out            = (float*)d_out;

    (void)in_sizes; (void)n_in; (void)out_size;

    dim3 pgrid(32, 8);
    prep_kernel<<<pgrid, 256>>>(W, f_logits);

    dim3 grid(OUTN / OT, BB / BT);   // 32 x 32 = 1024 blocks
    qfbn_main_kernel<<<grid, 128>>>(h, bias, out);
}